// round 4
// baseline (speedup 1.0000x reference)
#include <cuda_runtime.h>

// EA-LSTM fused persistent kernel, round 3: gate-split across 3 warp groups.
// B=1024, T=365, Dd=32, Ds=27, H=256, 3H=768, O=1.
// Grid: 128 CTAs x 768 threads. CTA owns M=8 batch elements for the whole
// sequence. Group g in {0:f, 1:o, 2:g} owns gate columns [g*256, g*256+256)
// over the FULL reduction (x-part 32 k's + h-part 256 k's) -> only 4 u64
// accumulators/thread, ~24 warps/SM. Groups o,g publish raw sums via SMEM;
// group f combines, applies nonlinearities, updates c/h; group 1 stages
// x_{t+1}; group 2 computes the scalar output dot (from a transposed h copy)
// overlapped with the next step's accumulation.
// All accumulation in Blackwell packed fp32x2 (bit-exact fp32).

#define B_      1024
#define T_      365
#define DD      32
#define DS      27
#define H_      256
#define G3      768
#define M_      8
#define THREADS 768
#define CTAS    (B_ / M_)      // 128
#define OGS     257            // padded u64 stride for published gate sums
#define HT_S    264            // padded row stride for transposed h

typedef unsigned long long u64;

__device__ __forceinline__ u64 pack2(float lo, float hi) {
    u64 r; asm("mov.b64 %0, {%1, %2};" : "=l"(r) : "f"(lo), "f"(hi)); return r;
}
__device__ __forceinline__ void unpack2(u64 v, float& lo, float& hi) {
    asm("mov.b64 {%0, %1}, %2;" : "=f"(lo), "=f"(hi) : "l"(v));
}
__device__ __forceinline__ void fma2(u64& d, u64 a, u64 b) {
    asm("fma.rn.f32x2 %0, %1, %2, %0;" : "+l"(d) : "l"(a), "l"(b));
}

__device__ __forceinline__ float sigmoidf_(float x) {
    return __fdividef(1.0f, 1.0f + __expf(-x));
}
__device__ __forceinline__ float tanhf_(float x) {
    float e = __expf(-2.0f * x);
    return __fdividef(1.0f - e, 1.0f + e);
}

__global__ void __launch_bounds__(THREADS, 1)
ealstm_kernel(const float* __restrict__ xd,      // [B, T, DD]
              const float* __restrict__ xs,      // [B, DS]
              const float* __restrict__ Wih,     // [DD, 3H]
              const float* __restrict__ Whh,     // [H, 3H]
              const float* __restrict__ Wsh,     // [DS, H]
              const float* __restrict__ bias,    // [3H]
              const float* __restrict__ bias_s,  // [H]
              const float* __restrict__ Wout,    // [H, 1]
              const float* __restrict__ bout,    // [1]
              float* __restrict__ out)           // [B, T, 1]
{
    __shared__ float h_s[H_ * M_];        // h[k][m], stride 8 (vectorized reads)
    __shared__ float h_t[M_][HT_S];       // h transposed [m][col] for out-dot
    __shared__ float x_s[DD * M_];        // x_t[k][m], stride 8
    __shared__ u64   og_s[2][4][OGS];     // raw gate sums from groups o (0) and g (1)

    const int tid   = threadIdx.x;
    const int grp   = tid >> 8;           // 0: f, 1: o, 2: g
    const int col   = tid & 255;          // column within the gate slice
    const int gbase = grp << 8;           // gate slice base in [0, 768)
    const int b0    = blockIdx.x * M_;
    const int lane  = tid & 31;

    // zero initial hidden state
    for (int i = tid; i < H_ * M_; i += THREADS) h_s[i] = 0.0f;

    // stage x_t for t = 0 (group 1)
    if (grp == 1) {
        const int m = col >> 5, k = col & 31;
        x_s[k * M_ + m] = xd[((size_t)(b0 + m) * T_ + 0) * DD + k];
    }

    const float bcol = bias[gbase + col];   // this thread's gate bias

    // group f: cell state + entity-aware input gate
    float c_[M_], ig[M_];
    if (grp == 0) {
        float s[M_];
        #pragma unroll
        for (int m = 0; m < M_; m++) { s[m] = bias_s[col]; c_[m] = 0.0f; }
        #pragma unroll 1
        for (int k = 0; k < DS; k++) {
            const float w = Wsh[k * H_ + col];
            #pragma unroll
            for (int m = 0; m < M_; m++)
                s[m] = fmaf(xs[(b0 + m) * DS + k], w, s[m]);
        }
        #pragma unroll
        for (int m = 0; m < M_; m++) ig[m] = sigmoidf_(s[m]);
    }

    // group 2: output weights for the warp-level out-dot
    float wout[8];
    float b_out0 = 0.0f;
    if (grp == 2) {
        #pragma unroll
        for (int q = 0; q < 8; q++) wout[q] = Wout[lane + 32 * q];
        b_out0 = bout[0];
    }

    __syncthreads();

    for (int t = 0; t < T_; t++) {
        // ---- phase A: acc = bias + x_t @ W_ih[:,slice] + h @ W_hh[:,slice] ----
        u64 acc[4];
        {
            const u64 b2 = pack2(bcol, bcol);
            #pragma unroll
            for (int p = 0; p < 4; p++) acc[p] = b2;
        }

        // x contribution (W_ih slice stays hot in L1)
        {
            const float* wp = Wih + gbase + col;
            #pragma unroll 8
            for (int k = 0; k < DD; k++) {
                const float w  = __ldg(wp + k * G3);
                const u64   w2 = pack2(w, w);
                const ulonglong2 hA = *(const ulonglong2*)(x_s + k * M_);
                const ulonglong2 hB = *(const ulonglong2*)(x_s + k * M_ + 4);
                fma2(acc[0], w2, hA.x);
                fma2(acc[1], w2, hA.y);
                fma2(acc[2], w2, hB.x);
                fma2(acc[3], w2, hB.y);
            }
        }
        // h contribution (W_hh streams from L2)
        {
            const float* wp = Whh + gbase + col;
            #pragma unroll 8
            for (int k = 0; k < H_; k++) {
                const float w  = __ldcg(wp + k * G3);
                const u64   w2 = pack2(w, w);
                const ulonglong2 hA = *(const ulonglong2*)(h_s + k * M_);
                const ulonglong2 hB = *(const ulonglong2*)(h_s + k * M_ + 4);
                fma2(acc[0], w2, hA.x);
                fma2(acc[1], w2, hA.y);
                fma2(acc[2], w2, hB.x);
                fma2(acc[3], w2, hB.y);
            }
        }

        // groups o, g publish raw sums (conflict-free: consecutive cols)
        if (grp >= 1) {
            u64* dst = &og_s[grp - 1][0][col];
            #pragma unroll
            for (int p = 0; p < 4; p++) dst[p * OGS] = acc[p];
        }

        __syncthreads();   // sums published; all h_s/x_s reads of step t done

        if (grp == 0) {
            // ---- combine + state update (f in acc, o/g from SMEM) ----
            float hn[M_];
            #pragma unroll
            for (int p = 0; p < 4; p++) {
                float f0, f1, o0, o1, g0, g1;
                unpack2(acc[p], f0, f1);
                unpack2(og_s[0][p][col], o0, o1);
                unpack2(og_s[1][p][col], g0, g1);
                const int m0 = 2 * p, m1 = 2 * p + 1;
                c_[m0] = sigmoidf_(f0) * c_[m0] + ig[m0] * tanhf_(g0);
                c_[m1] = sigmoidf_(f1) * c_[m1] + ig[m1] * tanhf_(g1);
                hn[m0] = sigmoidf_(o0) * tanhf_(c_[m0]);
                hn[m1] = sigmoidf_(o1) * tanhf_(c_[m1]);
            }
            // publish h for next step's phase A (vectorized)
            float4 v0 = make_float4(hn[0], hn[1], hn[2], hn[3]);
            float4 v1 = make_float4(hn[4], hn[5], hn[6], hn[7]);
            *(float4*)(h_s + col * M_)     = v0;
            *(float4*)(h_s + col * M_ + 4) = v1;
            // transposed copy for the out-dot (conflict-free rows)
            #pragma unroll
            for (int m = 0; m < M_; m++) h_t[m][col] = hn[m];
        } else if (grp == 1) {
            // stage x for t+1
            if (t + 1 < T_) {
                const int m = col >> 5, k = col & 31;
                x_s[k * M_ + m] = xd[((size_t)(b0 + m) * T_ + (t + 1)) * DD + k];
            }
        }

        __syncthreads();   // h_s(t), h_t(t), x_s(t+1) published

        // ---- output dot (group 2, warps 0..7): overlaps next phase A ----
        if (grp == 2) {
            const int w = (tid >> 5) - 16;   // 0..7 = batch element m
            float a = 0.0f;
            #pragma unroll
            for (int q = 0; q < 8; q++)
                a = fmaf(h_t[w][lane + 32 * q], wout[q], a);
            #pragma unroll
            for (int off = 16; off > 0; off >>= 1)
                a += __shfl_down_sync(0xffffffffu, a, off);
            if (lane == 0)
                out[(size_t)(b0 + w) * T_ + t] = a + b_out0;
        }
        // h_t isn't rewritten until after sync1 of step t+1, so this read-after-
        // sync2 overlap is race-free; h_s/x_s are read-only during phase A.
    }
}

extern "C" void kernel_launch(void* const* d_in, const int* in_sizes, int n_in,
                              void* d_out, int out_size) {
    const float* xd     = (const float*)d_in[0];  // x_dynamic [1024,365,32]
    const float* xs     = (const float*)d_in[1];  // x_static  [1024,27]
    const float* Wih    = (const float*)d_in[2];  // [32,768]
    const float* Whh    = (const float*)d_in[3];  // [256,768]
    const float* Wsh    = (const float*)d_in[4];  // [27,256]
    const float* bias   = (const float*)d_in[5];  // [768]
    const float* bias_s = (const float*)d_in[6];  // [256]
    const float* Wout   = (const float*)d_in[7];  // [256,1]
    const float* bout   = (const float*)d_in[8];  // [1]
    float* out = (float*)d_out;                   // [1024,365,1]

    ealstm_kernel<<<CTAS, THREADS>>>(xd, xs, Wih, Whh, Wsh, bias, bias_s,
                                     Wout, bout, out);
}

// round 5
// speedup vs baseline: 1.5314x; 1.5314x over previous
#include <cuda_runtime.h>

// EA-LSTM fused persistent kernel, round 4: round-2 split-k layout + packed
// weights (float4 per column: f,o,g) + 128-bit SMEM h loads.
// B=1024, T=365, Dd=32, Ds=27, H=256, 3H=768, O=1.
// Grid: 128 CTAs x 512 threads, M=8 batch elems per CTA. Thread (grp,col):
//   grp 0: bias + x_t @ W_ih + h[k=0..111] @ W_hh   (all 3 gates of col)
//   grp 1:                    h[k=112..255] @ W_hh  -> partials via SMEM
// Weights are repacked once per launch by a helper kernel into
// [k][col] = float4(Wf, Wo, Wg, 0) so the hot loop does ONE LDG.128 and
// TWO LDS.128 per k instead of 3 LDG.32 + 4 LDS.64  (LSU inst 7 -> 3 per k,
// moving the kernel from LSU-bound to fma-bound).
// All accumulation in Blackwell packed fp32x2 (bit-exact fp32).

#define B_      1024
#define T_      365
#define DD      32
#define DS      27
#define H_      256
#define G3      768
#define M_      8
#define THREADS 512
#define CTAS    (B_ / M_)      // 128
#define PS_STRIDE 13           // padded partial stride (u64 per column)
#define KSPLIT  112            // group0 h-range [0,112), group1 [112,256)

typedef unsigned long long u64;

// packed weights: [k][col] = (Wf, Wo, Wg, 0) for column col
__device__ float4 WhhP[H_][256];   // 1 MB
__device__ float4 WihP[DD][256];   // 128 KB

__device__ __forceinline__ u64 pack2(float lo, float hi) {
    u64 r; asm("mov.b64 %0, {%1, %2};" : "=l"(r) : "f"(lo), "f"(hi)); return r;
}
__device__ __forceinline__ void unpack2(u64 v, float& lo, float& hi) {
    asm("mov.b64 {%0, %1}, %2;" : "=f"(lo), "=f"(hi) : "l"(v));
}
__device__ __forceinline__ void fma2(u64& d, u64 a, u64 b) {
    asm("fma.rn.f32x2 %0, %1, %2, %0;" : "+l"(d) : "l"(a), "l"(b));
}
__device__ __forceinline__ void add2(u64& d, u64 a) {
    asm("add.rn.f32x2 %0, %0, %1;" : "+l"(d) : "l"(a));
}
__device__ __forceinline__ float sigmoidf_(float x) {
    return __fdividef(1.0f, 1.0f + __expf(-x));
}
__device__ __forceinline__ float tanhf_(float x) {
    float e = __expf(-2.0f * x);
    return __fdividef(1.0f - e, 1.0f + e);
}

__global__ void __launch_bounds__(256)
repack_kernel(const float* __restrict__ Wih, const float* __restrict__ Whh) {
    const int i   = blockIdx.x * blockDim.x + threadIdx.x;  // 0 .. 288*256-1
    const int k   = i >> 8;
    const int col = i & 255;
    if (k < DD) {
        const float* s = Wih + k * G3;
        WihP[k][col] = make_float4(s[col], s[256 + col], s[512 + col], 0.0f);
    } else {
        const float* s = Whh + (k - DD) * G3;
        WhhP[k - DD][col] = make_float4(s[col], s[256 + col], s[512 + col], 0.0f);
    }
}

__global__ void __launch_bounds__(THREADS, 1)
ealstm_kernel(const float* __restrict__ xd,      // [B, T, DD]
              const float* __restrict__ xs,      // [B, DS]
              const float* __restrict__ Wsh,     // [DS, H]
              const float* __restrict__ bias,    // [3H]
              const float* __restrict__ bias_s,  // [H]
              const float* __restrict__ Wout,    // [H, 1]
              const float* __restrict__ bout,    // [1]
              float* __restrict__ out)           // [B, T, 1]
{
    __shared__ __align__(16) float h_s[H_ * M_];   // h[k][m], stride 8
    __shared__ __align__(16) float x_s[DD * M_];   // x_t[k][m], stride 8
    __shared__ float h_t[M_][264];                 // h transposed for out-dot
    __shared__ u64   p_s[H_ * PS_STRIDE];          // group-1 partial gate sums

    const int j    = threadIdx.x;
    const int grp  = j >> 8;                // 0 or 1
    const int col  = j & 255;               // gate/h column
    const int b0   = blockIdx.x * M_;
    const int lane = j & 31;
    const int warp = j >> 5;

    // zero initial hidden state
    for (int idx = j; idx < H_ * M_; idx += THREADS) h_s[idx] = 0.0f;

    // stage x_t for t = 0 (group 1's 256 threads)
    if (grp == 1) {
        const int m = col >> 5, k = col & 31;
        x_s[k * M_ + m] = xd[((size_t)(b0 + m) * T_ + 0) * DD + k];
    }

    // per-thread gate biases (group 0 seeds accumulators)
    float bf = 0.0f, bo = 0.0f, bg = 0.0f;
    if (grp == 0) { bf = bias[col]; bo = bias[H_ + col]; bg = bias[2 * H_ + col]; }

    // entity-aware input gate (group 0 only)
    float ig[M_];
    if (grp == 0) {
        float s[M_];
        #pragma unroll
        for (int m = 0; m < M_; m++) s[m] = bias_s[col];
        #pragma unroll 1
        for (int k = 0; k < DS; k++) {
            const float w = Wsh[k * H_ + col];
            #pragma unroll
            for (int m = 0; m < M_; m++)
                s[m] = fmaf(xs[(b0 + m) * DS + k], w, s[m]);
        }
        #pragma unroll
        for (int m = 0; m < M_; m++) ig[m] = sigmoidf_(s[m]);
    }

    // per-lane output weights for the warp-level out-dot
    float wout[8];
    #pragma unroll
    for (int q = 0; q < 8; q++) wout[q] = Wout[lane + 32 * q];
    const float b_out0 = bout[0];

    float c[M_];
    #pragma unroll
    for (int m = 0; m < M_; m++) c[m] = 0.0f;

    __syncthreads();

    for (int t = 0; t < T_; t++) {
        u64 aF[4], aO[4], aG[4];

        if (grp == 0) {
            const u64 bf2 = pack2(bf, bf), bo2 = pack2(bo, bo), bg2 = pack2(bg, bg);
            #pragma unroll
            for (int p = 0; p < 4; p++) { aF[p] = bf2; aO[p] = bo2; aG[p] = bg2; }

            // x contribution
            #pragma unroll 4
            for (int k = 0; k < DD; k++) {
                const float4 w = __ldcg(&WihP[k][col]);
                const u64 wf2 = pack2(w.x, w.x), wo2 = pack2(w.y, w.y), wg2 = pack2(w.z, w.z);
                const ulonglong2 hA = *(const ulonglong2*)(x_s + k * M_);
                const ulonglong2 hB = *(const ulonglong2*)(x_s + k * M_ + 4);
                fma2(aF[0], wf2, hA.x); fma2(aF[1], wf2, hA.y);
                fma2(aF[2], wf2, hB.x); fma2(aF[3], wf2, hB.y);
                fma2(aO[0], wo2, hA.x); fma2(aO[1], wo2, hA.y);
                fma2(aO[2], wo2, hB.x); fma2(aO[3], wo2, hB.y);
                fma2(aG[0], wg2, hA.x); fma2(aG[1], wg2, hA.y);
                fma2(aG[2], wg2, hB.x); fma2(aG[3], wg2, hB.y);
            }
            // h contribution, k in [0, KSPLIT)
            #pragma unroll 4
            for (int k = 0; k < KSPLIT; k++) {
                const float4 w = __ldcg(&WhhP[k][col]);
                const u64 wf2 = pack2(w.x, w.x), wo2 = pack2(w.y, w.y), wg2 = pack2(w.z, w.z);
                const ulonglong2 hA = *(const ulonglong2*)(h_s + k * M_);
                const ulonglong2 hB = *(const ulonglong2*)(h_s + k * M_ + 4);
                fma2(aF[0], wf2, hA.x); fma2(aF[1], wf2, hA.y);
                fma2(aF[2], wf2, hB.x); fma2(aF[3], wf2, hB.y);
                fma2(aO[0], wo2, hA.x); fma2(aO[1], wo2, hA.y);
                fma2(aO[2], wo2, hB.x); fma2(aO[3], wo2, hB.y);
                fma2(aG[0], wg2, hA.x); fma2(aG[1], wg2, hA.y);
                fma2(aG[2], wg2, hB.x); fma2(aG[3], wg2, hB.y);
            }
        } else {
            #pragma unroll
            for (int p = 0; p < 4; p++) { aF[p] = 0ull; aO[p] = 0ull; aG[p] = 0ull; }

            // h contribution, k in [KSPLIT, 256)
            #pragma unroll 4
            for (int k = KSPLIT; k < H_; k++) {
                const float4 w = __ldcg(&WhhP[k][col]);
                const u64 wf2 = pack2(w.x, w.x), wo2 = pack2(w.y, w.y), wg2 = pack2(w.z, w.z);
                const ulonglong2 hA = *(const ulonglong2*)(h_s + k * M_);
                const ulonglong2 hB = *(const ulonglong2*)(h_s + k * M_ + 4);
                fma2(aF[0], wf2, hA.x); fma2(aF[1], wf2, hA.y);
                fma2(aF[2], wf2, hB.x); fma2(aF[3], wf2, hB.y);
                fma2(aO[0], wo2, hA.x); fma2(aO[1], wo2, hA.y);
                fma2(aO[2], wo2, hB.x); fma2(aO[3], wo2, hB.y);
                fma2(aG[0], wg2, hA.x); fma2(aG[1], wg2, hA.y);
                fma2(aG[2], wg2, hB.x); fma2(aG[3], wg2, hB.y);
            }
            // publish partials
            u64* pp = p_s + col * PS_STRIDE;
            #pragma unroll
            for (int p = 0; p < 4; p++) {
                pp[p]     = aF[p];
                pp[4 + p] = aO[p];
                pp[8 + p] = aG[p];
            }
        }

        __syncthreads();   // partials published; h_s/x_s reads of step t done

        if (grp == 0) {
            // combine partials + state update
            const u64* pp = p_s + col * PS_STRIDE;
            #pragma unroll
            for (int p = 0; p < 4; p++) {
                add2(aF[p], pp[p]);
                add2(aO[p], pp[4 + p]);
                add2(aG[p], pp[8 + p]);
            }
            float hn[M_];
            #pragma unroll
            for (int p = 0; p < 4; p++) {
                float f0, f1, o0, o1, g0, g1;
                unpack2(aF[p], f0, f1);
                unpack2(aO[p], o0, o1);
                unpack2(aG[p], g0, g1);
                const int m0 = 2 * p, m1 = 2 * p + 1;
                c[m0] = sigmoidf_(f0) * c[m0] + ig[m0] * tanhf_(g0);
                c[m1] = sigmoidf_(f1) * c[m1] + ig[m1] * tanhf_(g1);
                hn[m0] = sigmoidf_(o0) * tanhf_(c[m0]);
                hn[m1] = sigmoidf_(o1) * tanhf_(c[m1]);
            }
            // publish h (vectorized, stride-8 aligned)
            *(float4*)(h_s + col * M_)     = make_float4(hn[0], hn[1], hn[2], hn[3]);
            *(float4*)(h_s + col * M_ + 4) = make_float4(hn[4], hn[5], hn[6], hn[7]);
            // transposed copy for the out-dot
            #pragma unroll
            for (int m = 0; m < M_; m++) h_t[m][col] = hn[m];
        } else {
            // stage x for t+1
            if (t + 1 < T_) {
                const int m = col >> 5, k = col & 31;
                x_s[k * M_ + m] = xd[((size_t)(b0 + m) * T_ + (t + 1)) * DD + k];
            }
        }

        __syncthreads();   // h_s(t), h_t(t), x_s(t+1) published

        // output dot: group-1 warps (8..15) own batch elems 0..7; overlaps
        // group 0's next-step accumulation only trivially, but keeps group 0
        // (which also does the state update) lighter.
        if (grp == 1) {
            const int w = warp - 8;   // 0..7 = batch element m
            float a = 0.0f;
            #pragma unroll
            for (int q = 0; q < 8; q++)
                a = fmaf(h_t[w][lane + 32 * q], wout[q], a);
            #pragma unroll
            for (int off = 16; off > 0; off >>= 1)
                a += __shfl_down_sync(0xffffffffu, a, off);
            if (lane == 0)
                out[(size_t)(b0 + w) * T_ + t] = a + b_out0;
        }
        // h_t isn't rewritten until after the next step's first sync, so this
        // post-sync read overlap is race-free.
    }
}

extern "C" void kernel_launch(void* const* d_in, const int* in_sizes, int n_in,
                              void* d_out, int out_size) {
    const float* xd     = (const float*)d_in[0];  // x_dynamic [1024,365,32]
    const float* xs     = (const float*)d_in[1];  // x_static  [1024,27]
    const float* Wih    = (const float*)d_in[2];  // [32,768]
    const float* Whh    = (const float*)d_in[3];  // [256,768]
    const float* Wsh    = (const float*)d_in[4];  // [27,256]
    const float* bias   = (const float*)d_in[5];  // [768]
    const float* bias_s = (const float*)d_in[6];  // [256]
    const float* Wout   = (const float*)d_in[7];  // [256,1]
    const float* bout   = (const float*)d_in[8];  // [1]
    float* out = (float*)d_out;                   // [1024,365,1]

    // repack weights into float4-per-column layout (runs every launch;
    // deterministic, graph-capturable, no allocation)
    repack_kernel<<<(H_ + DD), 256>>>(Wih, Whh);
    ealstm_kernel<<<CTAS, THREADS>>>(xd, xs, Wsh, bias, bias_s,
                                     Wout, bout, out);
}